// round 11
// baseline (speedup 1.0000x reference)
#include <cuda_runtime.h>
#include <math.h>

#define NCODES 16384
#define CEMB   64
#define BB     8
#define ZSIZE  (BB*CEMB*4*16*16)   /* 524288 */
#define MAXN   8192

#define OFF_COMMIT 524288
#define OFF_PERP   524289
#define OFF_AVG    524290
#define OFF_USAGE  524291
#define OFF_IDX    540675

typedef unsigned long long ull;

__device__ float g_accu[ZSIZE];
__device__ float g_hup[ZSIZE];
__device__ float g_part[4][ZSIZE];
__device__ float g_q[MAXN*CEMB];
__device__ ull   g_key[MAXN];
__device__ float g_embT[CEMB*NCODES];
__device__ float g_esq[NCODES];
__device__ ull   g_Wt2[4*64*27*32];   /* [q][ci][k][pair p] : (c=p, c=p+32) */
__device__ float g_commit;
__device__ int   g_counts[NCODES];

#define FMA2(d,a,b) asm("fma.rn.f32x2 %0, %1, %2, %3;" : "=l"(d) : "l"(a), "l"(b), "l"(d))

__device__ __forceinline__ ull dup32(float v) {
    unsigned u = __float_as_uint(v);
    return ((ull)u << 32) | u;
}

// ---------------- fused setup (also does scale-0 pool: accu==0) ----------------
__global__ void k_setup(const float* __restrict__ z, const float* __restrict__ emb,
                        const float* __restrict__ Wq) {
    int tid = blockIdx.x*256 + threadIdx.x;   // 0..1048575
    {
        int k = tid >> 14, c = tid & (NCODES-1);
        g_embT[tid] = emb[c*CEMB + k];
    }
    if (tid < NCODES) {
        const float4* p = reinterpret_cast<const float4*>(emb + tid*CEMB);
        float s = 0.f;
        #pragma unroll
        for (int i = 0; i < 16; i++) {
            float4 v = p[i];
            s += v.x*v.x + v.y*v.y + v.z*v.z + v.w*v.w;
        }
        g_esq[tid] = s;
        g_counts[tid] = 0;
    }
    if (tid < 4*64*27*32) {
        int p = tid & 31;
        int r = tid >> 5;
        int k = r % 27;
        int r2 = r / 27;
        int ci = r2 % 64;
        int q  = r2 / 64;
        float lo = Wq[((q*64 + p     )*64 + ci)*27 + k];
        float hi = Wq[((q*64 + p + 32)*64 + ci)*27 + k];
        g_Wt2[tid] = ((ull)__float_as_uint(hi) << 32) | __float_as_uint(lo);
    }
    if (tid < ZSIZE) g_accu[tid] = 0.f;
    // scale-0 pool: q[b*64+c] = mean(z[b,c,:,:,:]) ; one warp per (b,c)
    if (tid < 512*32) {
        int lane = tid & 31;
        int gw = tid >> 5;
        int c = gw & 63, b = gw >> 6;
        const float* zp = z + (b*64 + c)*1024;
        float sum = 0.f;
        for (int i = lane; i < 1024; i += 32) sum += zp[i];
        #pragma unroll
        for (int o = 16; o; o >>= 1) sum += __shfl_down_sync(0xffffffffu, sum, o);
        if (lane == 0) g_q[b*64 + c] = sum * (1.0f/1024.0f);
    }
    if (tid < 8) g_key[tid] = 0xFFFFFFFFFFFFFFFFull;
    if (tid == 0) g_commit = 0.f;
}

// ---- pool window bounds ----
__device__ __forceinline__ void pool_bounds(int n, int tpn, int pn,
        int& b, int& sT, int& eT, int& sH, int& eH, int& sW, int& eW) {
    int x = n % pn;
    int v = (n/pn) % pn;
    int r2 = n/(pn*pn);
    int u = r2 % tpn;
    b = r2 / tpn;
    sT = (u*4)/tpn;  eT = ((u+1)*4  + tpn-1)/tpn;
    sH = (v*16)/pn;  eH = ((v+1)*16 + pn-1)/pn;
    sW = (x*16)/pn;  eW = ((x+1)*16 + pn-1)/pn;
}

// -------- pool, thread version (large N / small windows) --------
__global__ void k_pool(const float* __restrict__ z, int tpn, int pn, int N) {
    int tid = blockIdx.x*256 + threadIdx.x;
    if (tid >= N*64) return;
    int c = tid & 63;
    int n = tid >> 6;
    if (c == 0) g_key[n] = 0xFFFFFFFFFFFFFFFFull;
    int b, sT, eT, sH, eH, sW, eW;
    pool_bounds(n, tpn, pn, b, sT, eT, sH, eH, sW, eW);
    const float* zp = z      + (b*64 + c)*1024;
    const float* ap = g_accu + (b*64 + c)*1024;
    float sum = 0.f;
    for (int t = sT; t < eT; t++)
        for (int h = sH; h < eH; h++)
            for (int w = sW; w < eW; w++) {
                int o = t*256 + h*16 + w;
                sum += zp[o] - ap[o];
            }
    float inv = (1.f/(float)(eT-sT))*(1.f/(float)(eH-sH))*(1.f/(float)(eW-sW));
    g_q[n*64 + c] = sum * inv;
}

// -------- pool, warp version (small N / big windows) --------
__global__ void k_pool_warp(const float* __restrict__ z, int tpn, int pn, int N) {
    int gw = (blockIdx.x*256 + threadIdx.x) >> 5;
    int lane = threadIdx.x & 31;
    if (gw >= N*64) return;
    int c = gw & 63;
    int n = gw >> 6;
    if (c == 0 && lane == 0) g_key[n] = 0xFFFFFFFFFFFFFFFFull;
    int b, sT, eT, sH, eH, sW, eW;
    pool_bounds(n, tpn, pn, b, sT, eT, sH, eH, sW, eW);
    int nT = eT-sT, nH = eH-sH, nW = eW-sW;
    int tot = nT*nH*nW;
    const float* zp = z      + (b*64 + c)*1024;
    const float* ap = g_accu + (b*64 + c)*1024;
    float sum = 0.f;
    for (int i = lane; i < tot; i += 32) {
        int w = i % nW;
        int r = i / nW;
        int h = r % nH;
        int t = r / nH;
        int o = (sT+t)*256 + (sH+h)*16 + (sW+w);
        sum += zp[o] - ap[o];
    }
    #pragma unroll
    for (int o = 16; o; o >>= 1) sum += __shfl_down_sync(0xffffffffu, sum, o);
    if (lane == 0) {
        float inv = (1.f/(float)nT)*(1.f/(float)nH)*(1.f/(float)nW);
        g_q[n*64 + c] = sum * inv;
    }
}

// ---- shared: per-query key reduce + atomicMin ----
__device__ __forceinline__ void key_reduce_commit(float best, int bi, int q, int N, int tx) {
    unsigned ub = __float_as_uint(best);
    ub = (ub & 0x80000000u) ? ~ub : (ub | 0x80000000u);
    ull key = ((ull)ub << 32) | (unsigned)bi;
    #pragma unroll
    for (int o = 16; o; o >>= 1) {
        ull ok = __shfl_down_sync(0xffffffffu, key, o);
        if (ok < key) key = ok;
    }
    if ((tx & 31) == 0 && q < N) atomicMin(&g_key[q], key);
}

// -------- NN search: 32 queries x 512 codes per block, packed f32x2 FMA --------
__global__ void __launch_bounds__(256, 2) k_nn(int N) {
    int tx = threadIdx.x;
    int ty = threadIdx.y;
    int qbase = blockIdx.y << 5;
    int cbase = (blockIdx.x << 9) + (tx << 3);
    __shared__ __align__(16) ull qs[32*64];
    int tid = ty*64 + tx;
    for (int i = tid; i < 2048; i += 256) {
        int qr = qbase + (i >> 6);
        qs[i] = dup32((qr < N) ? g_q[qr*64 + (i & 63)] : 0.f);
    }
    __syncthreads();
    ull acc[8][4];
    #pragma unroll
    for (int j = 0; j < 8; j++)
        #pragma unroll
        for (int cc = 0; cc < 4; cc++) acc[j][cc] = 0ull;
    const ulonglong2* e2 = reinterpret_cast<const ulonglong2*>(g_embT);
    int coff = (blockIdx.x << 7) + (tx << 1);
    const ulonglong2* qb2 = reinterpret_cast<const ulonglong2*>(qs) + (ty << 3)*32;
    #pragma unroll 2
    for (int k = 0; k < 64; k += 2) {
        ulonglong2 ea0 = e2[(k << 12) + coff];
        ulonglong2 eb0 = e2[(k << 12) + coff + 1];
        ulonglong2 ea1 = e2[((k+1) << 12) + coff];
        ulonglong2 eb1 = e2[((k+1) << 12) + coff + 1];
        #pragma unroll
        for (int j = 0; j < 8; j++) {
            ulonglong2 qp = qb2[(j << 5) + (k >> 1)];
            FMA2(acc[j][0], qp.x, ea0.x);
            FMA2(acc[j][1], qp.x, ea0.y);
            FMA2(acc[j][2], qp.x, eb0.x);
            FMA2(acc[j][3], qp.x, eb0.y);
            FMA2(acc[j][0], qp.y, ea1.x);
            FMA2(acc[j][1], qp.y, ea1.y);
            FMA2(acc[j][2], qp.y, eb1.x);
            FMA2(acc[j][3], qp.y, eb1.y);
        }
    }
    const float4* s4 = reinterpret_cast<const float4*>(g_esq);
    float4 qa = s4[cbase >> 2];
    float4 qbv = s4[(cbase >> 2) + 1];
    float es[8] = {qa.x, qa.y, qa.z, qa.w, qbv.x, qbv.y, qbv.z, qbv.w};
    #pragma unroll
    for (int j = 0; j < 8; j++) {
        float best = 3.4e38f; int bi = 0;
        #pragma unroll
        for (int cc = 0; cc < 4; cc++) {
            float d0 = __uint_as_float((unsigned)(acc[j][cc] & 0xffffffffull));
            float d1 = __uint_as_float((unsigned)(acc[j][cc] >> 32));
            float s0 = fmaf(-2.f, d0, es[2*cc]);
            float s1 = fmaf(-2.f, d1, es[2*cc+1]);
            if (s0 < best) { best = s0; bi = cbase + 2*cc; }
            if (s1 < best) { best = s1; bi = cbase + 2*cc + 1; }
        }
        key_reduce_commit(best, bi, qbase + (ty << 3) + j, N, tx);
    }
}

// -------- NN search, small-N: 32 q x 128 codes per block (2 codes/thread) --------
__global__ void __launch_bounds__(256, 2) k_nn_small(int N) {
    int tx = threadIdx.x;
    int ty = threadIdx.y;
    int qbase = blockIdx.y << 5;
    int cbase = (blockIdx.x << 7) + (tx << 1);
    __shared__ __align__(16) ull qs[32*64];
    int tid = ty*64 + tx;
    for (int i = tid; i < 2048; i += 256) {
        int qr = qbase + (i >> 6);
        qs[i] = dup32((qr < N) ? g_q[qr*64 + (i & 63)] : 0.f);
    }
    __syncthreads();
    ull acc[8];
    #pragma unroll
    for (int j = 0; j < 8; j++) acc[j] = 0ull;
    const ull* e1 = reinterpret_cast<const ull*>(g_embT);
    int coff = (blockIdx.x << 6) + tx;        // in ull units; row = 8192 ull
    const ulonglong2* qb2 = reinterpret_cast<const ulonglong2*>(qs) + (ty << 3)*32;
    #pragma unroll 4
    for (int k = 0; k < 64; k += 2) {
        ull ek0 = e1[(k << 13) + coff];
        ull ek1 = e1[((k+1) << 13) + coff];
        #pragma unroll
        for (int j = 0; j < 8; j++) {
            ulonglong2 qp = qb2[(j << 5) + (k >> 1)];
            FMA2(acc[j], qp.x, ek0);
            FMA2(acc[j], qp.y, ek1);
        }
    }
    const float2* s2 = reinterpret_cast<const float2*>(g_esq);
    float2 ev = s2[cbase >> 1];
    #pragma unroll
    for (int j = 0; j < 8; j++) {
        float d0 = __uint_as_float((unsigned)(acc[j] & 0xffffffffull));
        float d1 = __uint_as_float((unsigned)(acc[j] >> 32));
        float s0 = fmaf(-2.f, d0, ev.x);
        float s1 = fmaf(-2.f, d1, ev.y);
        float best = s0; int bi = cbase;
        if (s1 < best) { best = s1; bi = cbase + 1; }
        key_reduce_commit(best, bi, qbase + (ty << 3) + j, N, tx);
    }
}

// -------- upsample (trilinear), channel-pair per thread, float2 gathers --------
__device__ __forceinline__ void axw(int i, int in, int out, int& i0, int& i1, float& f) {
    float scale = (float)in / (float)out;
    float src = fmaxf((i + 0.5f)*scale - 0.5f, 0.f);
    i0 = (int)src;
    if (i0 > in-1) i0 = in-1;
    i1 = i0 + 1; if (i1 > in-1) i1 = in-1;
    f = src - (float)i0;
}

__global__ void k_upsample(const float* __restrict__ emb, int tpn, int pn, int N,
                           float* __restrict__ idx_out) {
    int tid = blockIdx.x*256 + threadIdx.x;     // 0..262143
    if (tid >= ZSIZE/2) return;
    if (tid < N) idx_out[tid] = (float)(unsigned)(g_key[tid] & 0xffffffffull);
    int c = (tid & 31) << 1;      // channel pair c, c+1
    int s = tid >> 5;
    int w = s & 15, h = (s >> 4) & 15, t = (s >> 8) & 3, b = s >> 10;
    int t0,t1,h0,h1,w0,w1; float ft,fh,fw;
    axw(t, tpn,  4, t0, t1, ft);
    axw(h, pn,  16, h0, h1, fh);
    axw(w, pn,  16, w0, w1, fw);
    int ts[2]  = {t0, t1}; float twt[2] = {1.f-ft, ft};
    int hs[2]  = {h0, h1}; float hwt[2] = {1.f-fh, fh};
    int wss[2] = {w0, w1}; float wwt[2] = {1.f-fw, fw};
    int nb = b*tpn;
    float v0 = 0.f, v1 = 0.f;
    #pragma unroll
    for (int a = 0; a < 2; a++)
        #pragma unroll
        for (int d = 0; d < 2; d++)
            #pragma unroll
            for (int e = 0; e < 2; e++) {
                float wt = twt[a]*hwt[d]*wwt[e];
                int n = ((nb + ts[a])*pn + hs[d])*pn + wss[e];
                int id = (int)(unsigned)(g_key[n] & 0xffffffffull);
                float2 ev = *reinterpret_cast<const float2*>(emb + id*64 + c);
                v0 = fmaf(wt, ev.x, v0);
                v1 = fmaf(wt, ev.y, v1);
            }
    int base = ((b*64 + c)*4 + t)*256 + h*16 + w;
    g_hup[base] = v0;
    g_hup[base + 1024] = v1;
}

// ---- conv3d partial: 16 input channels per block (split-K x4, grid 512) ----
__global__ void __launch_bounds__(256) k_conv_part(int qi) {
    int b = blockIdx.x, t = blockIdx.y;
    int hq = blockIdx.z & 3, part = blockIdx.z >> 2;   // part 0..3
    int tid = threadIdx.x;
    int p = tid & 31;                 // channel pair: c0=p, c1=p+32
    int hh = (tid >> 5) & 3;
    int wseg = tid >> 7;              // 0 or 1
    int h = hq*4 + hh;
    int wbase = wseg << 3;
    __shared__ __align__(16) ull wsu[4][27*32];
    __shared__ __align__(16) ull xsu[4][288];
    ull acc[8];
    #pragma unroll
    for (int i = 0; i < 8; i++) acc[i] = 0ull;
    int cb0 = part << 4;
    for (int cb = cb0; cb < cb0 + 16; cb += 4) {
        __syncthreads();
        const ull* wsrc = g_Wt2 + (size_t)((qi*64 + cb)*27)*32;
        for (int i = tid; i < 4*27*32; i += 256) wsu[0][i] = wsrc[i];
        for (int i = tid; i < 4*288; i += 256) {
            int cib = i / 288, r = i % 288;
            int td = r/96, rem = r%96, hd = rem/16, wd = rem & 15;
            int tt = t + td - 1;
            int hg = hq*4 + hd - 1;
            float x = (tt >= 0 && tt < 4 && hg >= 0 && hg < 16)
                      ? g_hup[((b*64 + cb + cib)*4 + tt)*256 + hg*16 + wd] : 0.f;
            xsu[cib][r] = dup32(x);
        }
        __syncthreads();
        #pragma unroll
        for (int cib = 0; cib < 4; cib++) {
            #pragma unroll
            for (int kd = 0; kd < 3; kd++) {
                #pragma unroll
                for (int kh = 0; kh < 3; kh++) {
                    const ull* xrow = xsu[cib] + (kd*6 + hh + kh)*16;
                    ull r[10];
                    r[0] = (wseg == 0) ? 0ull : xrow[wbase - 1];
                    #pragma unroll
                    for (int j = 1; j <= 8; j++) r[j] = xrow[wbase - 1 + j];
                    r[9] = (wseg == 1) ? 0ull : xrow[wbase + 8];
                    const ull* wp = wsu[cib] + (kd*9 + kh*3)*32 + p;
                    #pragma unroll
                    for (int kw = 0; kw < 3; kw++) {
                        ull wv = wp[kw*32];
                        #pragma unroll
                        for (int w2 = 0; w2 < 8; w2++)
                            FMA2(acc[w2], wv, r[w2+kw]);
                    }
                }
            }
        }
    }
    int base0 = ((b*64 + p     )*4 + t)*256 + h*16 + wbase;
    int base1 = ((b*64 + p + 32)*4 + t)*256 + h*16 + wbase;
    float* dst = g_part[part];
    #pragma unroll
    for (int w2 = 0; w2 < 8; w2++) {
        dst[base0 + w2] = __uint_as_float((unsigned)(acc[w2] & 0xffffffffull));
        dst[base1 + w2] = __uint_as_float((unsigned)(acc[w2] >> 32));
    }
}

// ---- conv epilogue: combine 4 partials, mix, accumulate, commit ----
__global__ void __launch_bounds__(256) k_conv_fin(const float* __restrict__ z,
                                                  const float* __restrict__ bq, int qi) {
    int i4 = blockIdx.x*256 + threadIdx.x;   // 0..131071
    int base = i4 << 2;
    float4 p0 = *reinterpret_cast<const float4*>(&g_part[0][base]);
    float4 p1 = *reinterpret_cast<const float4*>(&g_part[1][base]);
    float4 p2 = *reinterpret_cast<const float4*>(&g_part[2][base]);
    float4 p3 = *reinterpret_cast<const float4*>(&g_part[3][base]);
    int c = (base >> 10) & 63;
    float bias = bq[qi*64 + c];
    float4 hv = *reinterpret_cast<const float4*>(&g_hup[base]);
    float4 av = *reinterpret_cast<const float4*>(&g_accu[base]);
    float4 zv = *reinterpret_cast<const float4*>(&z[base]);
    float s0 = ((p0.x + p1.x) + p2.x) + p3.x;
    float s1 = ((p0.y + p1.y) + p2.y) + p3.y;
    float s2 = ((p0.z + p1.z) + p2.z) + p3.z;
    float s3 = ((p0.w + p1.w) + p2.w) + p3.w;
    float4 nv;
    nv.x = av.x + (0.5f*hv.x + 0.5f*(s0 + bias));
    nv.y = av.y + (0.5f*hv.y + 0.5f*(s1 + bias));
    nv.z = av.z + (0.5f*hv.z + 0.5f*(s2 + bias));
    nv.w = av.w + (0.5f*hv.w + 0.5f*(s3 + bias));
    *reinterpret_cast<float4*>(&g_accu[base]) = nv;
    float d0 = nv.x - zv.x, d1 = nv.y - zv.y, d2 = nv.z - zv.z, d3 = nv.w - zv.w;
    float lsum = d0*d0 + d1*d1 + d2*d2 + d3*d3;
    #pragma unroll
    for (int o = 16; o; o >>= 1) lsum += __shfl_down_sync(0xffffffffu, lsum, o);
    __shared__ float red[8];
    if ((threadIdx.x & 31) == 0) red[threadIdx.x >> 5] = lsum;
    __syncthreads();
    if (threadIdx.x < 8) {
        float v = red[threadIdx.x];
        #pragma unroll
        for (int o = 4; o; o >>= 1) v += __shfl_down_sync(0xffu, v, o);
        if (threadIdx.x == 0) atomicAdd(&g_commit, v);
    }
}

// ---------------- finalization ----------------
__global__ void k_copy(const float* __restrict__ z, float* __restrict__ out) {
    int i = blockIdx.x*256 + threadIdx.x;
    if (i < 8192) atomicAdd(&g_counts[(int)(unsigned)(g_key[i] & 0xffffffffull)], 1);
    if (i < ZSIZE) out[i] = (g_accu[i] - z[i]) + z[i];
}

__global__ void k_stats(float* __restrict__ out) {
    int tid = threadIdx.x;
    float ent = 0.f; int cnt = 0;
    for (int i = tid; i < NCODES; i += 256) {
        float p = (float)g_counts[i] * (1.0f/8192.0f);
        out[OFF_USAGE + i] = p;
        ent += p * logf(p + 1e-10f);
        if (p > (1.0f/16384.0f)) cnt++;
    }
    __shared__ float se[256];
    __shared__ int   sc[256];
    se[tid] = ent; sc[tid] = cnt;
    __syncthreads();
    for (int o = 128; o; o >>= 1) {
        if (tid < o) { se[tid] += se[tid+o]; sc[tid] += sc[tid+o]; }
        __syncthreads();
    }
    if (tid == 0) {
        out[OFF_COMMIT] = g_commit * (0.25f/524288.0f) * 0.1f;
        out[OFF_PERP]   = expf(-se[0]);
        out[OFF_AVG]    = (float)sc[0] / 16384.0f;
    }
}

extern "C" void kernel_launch(void* const* d_in, const int* in_sizes, int n_in,
                              void* d_out, int out_size) {
    const float* z   = nullptr;
    const float* emb = nullptr;
    const float* Wq  = nullptr;
    const float* bq  = nullptr;
    for (int i = 0; i < n_in; i++) {
        switch (in_sizes[i]) {
            case 524288:  z   = (const float*)d_in[i]; break;
            case 1048576: emb = (const float*)d_in[i]; break;
            case 442368:  Wq  = (const float*)d_in[i]; break;
            case 256:     bq  = (const float*)d_in[i]; break;
        }
    }
    float* out = (float*)d_out;

    static const int TPN[10] = {1,1,2,2,2,4,4,4,4,4};
    static const int VPN[10] = {1,2,3,4,5,6,8,10,13,16};
    static const int QIA[10] = {0,0,1,1,1,2,2,3,3,3};

    k_setup<<<4096, 256>>>(z, emb, Wq);

    int off = OFF_IDX;
    for (int si = 0; si < 10; si++) {
        int tpn = TPN[si], pn = VPN[si];
        int N = BB * tpn * pn * pn;
        if (si > 0) {
            if (N <= 512)
                k_pool_warp<<<(N*64*32 + 255)/256, 256>>>(z, tpn, pn, N);
            else
                k_pool<<<(N*64 + 255)/256, 256>>>(z, tpn, pn, N);
        }
        dim3 bnn(64, 4);
        if (N <= 448) {
            dim3 gnn(128, (N + 31)/32);
            k_nn_small<<<gnn, bnn>>>(N);
        } else {
            dim3 gnn(32, (N + 31)/32);
            k_nn<<<gnn, bnn>>>(N);
        }
        k_upsample<<<(ZSIZE/2 + 255)/256, 256>>>(emb, tpn, pn, N, out + off);
        off += N;
        k_conv_part<<<dim3(8,4,16), 256>>>(QIA[si]);
        k_conv_fin<<<ZSIZE/1024, 256>>>(z, bq, QIA[si]);
    }
    k_copy<<<(ZSIZE + 255)/256, 256>>>(z, out);
    k_stats<<<1, 256>>>(out);
}

// round 12
// speedup vs baseline: 1.0204x; 1.0204x over previous
#include <cuda_runtime.h>
#include <math.h>

#define NCODES 16384
#define CEMB   64
#define BB     8
#define ZSIZE  (BB*CEMB*4*16*16)   /* 524288 */
#define MAXN   8192

#define OFF_COMMIT 524288
#define OFF_PERP   524289
#define OFF_AVG    524290
#define OFF_USAGE  524291
#define OFF_IDX    540675

typedef unsigned long long ull;

__device__ float g_accu[ZSIZE];
__device__ float g_hup[ZSIZE];
__device__ float g_part[4][ZSIZE];
__device__ float g_q[MAXN*CEMB];
__device__ ull   g_key[MAXN];
__device__ float g_embT[CEMB*NCODES];
__device__ float g_esq[NCODES];
__device__ ull   g_Wt2[4*64*27*32];   /* [q][ci][k][pair p] : (c=p, c=p+32) */
__device__ float g_commit;
__device__ int   g_counts[NCODES];

#define FMA2(d,a,b) asm("fma.rn.f32x2 %0, %1, %2, %3;" : "=l"(d) : "l"(a), "l"(b), "l"(d))

__device__ __forceinline__ ull dup32(float v) {
    unsigned u = __float_as_uint(v);
    return ((ull)u << 32) | u;
}

// ---------------- fused setup (also does scale-0 pool: accu==0) ----------------
__global__ void k_setup(const float* __restrict__ z, const float* __restrict__ emb,
                        const float* __restrict__ Wq) {
    int tid = blockIdx.x*256 + threadIdx.x;   // 0..1048575
    {
        int k = tid >> 14, c = tid & (NCODES-1);
        g_embT[tid] = emb[c*CEMB + k];
    }
    if (tid < NCODES) {
        const float4* p = reinterpret_cast<const float4*>(emb + tid*CEMB);
        float s = 0.f;
        #pragma unroll
        for (int i = 0; i < 16; i++) {
            float4 v = p[i];
            s += v.x*v.x + v.y*v.y + v.z*v.z + v.w*v.w;
        }
        g_esq[tid] = s;
        g_counts[tid] = 0;
    }
    if (tid < 4*64*27*32) {
        int p = tid & 31;
        int r = tid >> 5;
        int k = r % 27;
        int r2 = r / 27;
        int ci = r2 % 64;
        int q  = r2 / 64;
        float lo = Wq[((q*64 + p     )*64 + ci)*27 + k];
        float hi = Wq[((q*64 + p + 32)*64 + ci)*27 + k];
        g_Wt2[tid] = ((ull)__float_as_uint(hi) << 32) | __float_as_uint(lo);
    }
    if (tid < ZSIZE) g_accu[tid] = 0.f;
    // scale-0 pool: q[b*64+c] = mean(z[b,c,:,:,:]) ; one warp per (b,c)
    if (tid < 512*32) {
        int lane = tid & 31;
        int gw = tid >> 5;
        int c = gw & 63, b = gw >> 6;
        const float* zp = z + (b*64 + c)*1024;
        float sum = 0.f;
        for (int i = lane; i < 1024; i += 32) sum += zp[i];
        #pragma unroll
        for (int o = 16; o; o >>= 1) sum += __shfl_down_sync(0xffffffffu, sum, o);
        if (lane == 0) g_q[b*64 + c] = sum * (1.0f/1024.0f);
    }
    if (tid < 8) g_key[tid] = 0xFFFFFFFFFFFFFFFFull;
    if (tid == 0) g_commit = 0.f;
}

// ---- pool window bounds ----
__device__ __forceinline__ void pool_bounds(int n, int tpn, int pn,
        int& b, int& sT, int& eT, int& sH, int& eH, int& sW, int& eW) {
    int x = n % pn;
    int v = (n/pn) % pn;
    int r2 = n/(pn*pn);
    int u = r2 % tpn;
    b = r2 / tpn;
    sT = (u*4)/tpn;  eT = ((u+1)*4  + tpn-1)/tpn;
    sH = (v*16)/pn;  eH = ((v+1)*16 + pn-1)/pn;
    sW = (x*16)/pn;  eW = ((x+1)*16 + pn-1)/pn;
}

// -------- pool, thread version (large N / small windows) --------
__global__ void k_pool(const float* __restrict__ z, int tpn, int pn, int N) {
    int tid = blockIdx.x*256 + threadIdx.x;
    if (tid >= N*64) return;
    int c = tid & 63;
    int n = tid >> 6;
    if (c == 0) g_key[n] = 0xFFFFFFFFFFFFFFFFull;
    int b, sT, eT, sH, eH, sW, eW;
    pool_bounds(n, tpn, pn, b, sT, eT, sH, eH, sW, eW);
    const float* zp = z      + (b*64 + c)*1024;
    const float* ap = g_accu + (b*64 + c)*1024;
    float sum = 0.f;
    for (int t = sT; t < eT; t++)
        for (int h = sH; h < eH; h++)
            for (int w = sW; w < eW; w++) {
                int o = t*256 + h*16 + w;
                sum += zp[o] - ap[o];
            }
    float inv = (1.f/(float)(eT-sT))*(1.f/(float)(eH-sH))*(1.f/(float)(eW-sW));
    g_q[n*64 + c] = sum * inv;
}

// -------- pool, warp version (small N / big windows) --------
__global__ void k_pool_warp(const float* __restrict__ z, int tpn, int pn, int N) {
    int gw = (blockIdx.x*256 + threadIdx.x) >> 5;
    int lane = threadIdx.x & 31;
    if (gw >= N*64) return;
    int c = gw & 63;
    int n = gw >> 6;
    if (c == 0 && lane == 0) g_key[n] = 0xFFFFFFFFFFFFFFFFull;
    int b, sT, eT, sH, eH, sW, eW;
    pool_bounds(n, tpn, pn, b, sT, eT, sH, eH, sW, eW);
    int nT = eT-sT, nH = eH-sH, nW = eW-sW;
    int tot = nT*nH*nW;
    const float* zp = z      + (b*64 + c)*1024;
    const float* ap = g_accu + (b*64 + c)*1024;
    float sum = 0.f;
    for (int i = lane; i < tot; i += 32) {
        int w = i % nW;
        int r = i / nW;
        int h = r % nH;
        int t = r / nH;
        int o = (sT+t)*256 + (sH+h)*16 + (sW+w);
        sum += zp[o] - ap[o];
    }
    #pragma unroll
    for (int o = 16; o; o >>= 1) sum += __shfl_down_sync(0xffffffffu, sum, o);
    if (lane == 0) {
        float inv = (1.f/(float)nT)*(1.f/(float)nH)*(1.f/(float)nW);
        g_q[n*64 + c] = sum * inv;
    }
}

// ---- shared: per-query key reduce + atomicMin ----
__device__ __forceinline__ void key_reduce_commit(float best, int bi, int q, int N, int tx) {
    unsigned ub = __float_as_uint(best);
    ub = (ub & 0x80000000u) ? ~ub : (ub | 0x80000000u);
    ull key = ((ull)ub << 32) | (unsigned)bi;
    #pragma unroll
    for (int o = 16; o; o >>= 1) {
        ull ok = __shfl_down_sync(0xffffffffu, key, o);
        if (ok < key) key = ok;
    }
    if ((tx & 31) == 0 && q < N) atomicMin(&g_key[q], key);
}

// -------- NN search: 32 queries x 512 codes per block, packed f32x2 FMA --------
__global__ void __launch_bounds__(256, 2) k_nn(int N) {
    int tx = threadIdx.x;
    int ty = threadIdx.y;
    int qbase = blockIdx.y << 5;
    int cbase = (blockIdx.x << 9) + (tx << 3);
    __shared__ __align__(16) ull qs[32*64];
    int tid = ty*64 + tx;
    for (int i = tid; i < 2048; i += 256) {
        int qr = qbase + (i >> 6);
        qs[i] = dup32((qr < N) ? g_q[qr*64 + (i & 63)] : 0.f);
    }
    __syncthreads();
    ull acc[8][4];
    #pragma unroll
    for (int j = 0; j < 8; j++)
        #pragma unroll
        for (int cc = 0; cc < 4; cc++) acc[j][cc] = 0ull;
    const ulonglong2* e2 = reinterpret_cast<const ulonglong2*>(g_embT);
    int coff = (blockIdx.x << 7) + (tx << 1);
    const ulonglong2* qb2 = reinterpret_cast<const ulonglong2*>(qs) + (ty << 3)*32;
    #pragma unroll 2
    for (int k = 0; k < 64; k += 2) {
        ulonglong2 ea0 = e2[(k << 12) + coff];
        ulonglong2 eb0 = e2[(k << 12) + coff + 1];
        ulonglong2 ea1 = e2[((k+1) << 12) + coff];
        ulonglong2 eb1 = e2[((k+1) << 12) + coff + 1];
        #pragma unroll
        for (int j = 0; j < 8; j++) {
            ulonglong2 qp = qb2[(j << 5) + (k >> 1)];
            FMA2(acc[j][0], qp.x, ea0.x);
            FMA2(acc[j][1], qp.x, ea0.y);
            FMA2(acc[j][2], qp.x, eb0.x);
            FMA2(acc[j][3], qp.x, eb0.y);
            FMA2(acc[j][0], qp.y, ea1.x);
            FMA2(acc[j][1], qp.y, ea1.y);
            FMA2(acc[j][2], qp.y, eb1.x);
            FMA2(acc[j][3], qp.y, eb1.y);
        }
    }
    const float4* s4 = reinterpret_cast<const float4*>(g_esq);
    float4 qa = s4[cbase >> 2];
    float4 qbv = s4[(cbase >> 2) + 1];
    float es[8] = {qa.x, qa.y, qa.z, qa.w, qbv.x, qbv.y, qbv.z, qbv.w};
    #pragma unroll
    for (int j = 0; j < 8; j++) {
        float best = 3.4e38f; int bi = 0;
        #pragma unroll
        for (int cc = 0; cc < 4; cc++) {
            float d0 = __uint_as_float((unsigned)(acc[j][cc] & 0xffffffffull));
            float d1 = __uint_as_float((unsigned)(acc[j][cc] >> 32));
            float s0 = fmaf(-2.f, d0, es[2*cc]);
            float s1 = fmaf(-2.f, d1, es[2*cc+1]);
            if (s0 < best) { best = s0; bi = cbase + 2*cc; }
            if (s1 < best) { best = s1; bi = cbase + 2*cc + 1; }
        }
        key_reduce_commit(best, bi, qbase + (ty << 3) + j, N, tx);
    }
}

// -------- upsample (trilinear), channel-pair per thread, float2 gathers --------
__device__ __forceinline__ void axw(int i, int in, int out, int& i0, int& i1, float& f) {
    float scale = (float)in / (float)out;
    float src = fmaxf((i + 0.5f)*scale - 0.5f, 0.f);
    i0 = (int)src;
    if (i0 > in-1) i0 = in-1;
    i1 = i0 + 1; if (i1 > in-1) i1 = in-1;
    f = src - (float)i0;
}

__global__ void k_upsample(const float* __restrict__ emb, int tpn, int pn, int N,
                           float* __restrict__ idx_out) {
    int tid = blockIdx.x*256 + threadIdx.x;     // 0..262143
    if (tid >= ZSIZE/2) return;
    if (tid < N) idx_out[tid] = (float)(unsigned)(g_key[tid] & 0xffffffffull);
    int c = (tid & 31) << 1;      // channel pair c, c+1
    int s = tid >> 5;
    int w = s & 15, h = (s >> 4) & 15, t = (s >> 8) & 3, b = s >> 10;
    int t0,t1,h0,h1,w0,w1; float ft,fh,fw;
    axw(t, tpn,  4, t0, t1, ft);
    axw(h, pn,  16, h0, h1, fh);
    axw(w, pn,  16, w0, w1, fw);
    int ts[2]  = {t0, t1}; float twt[2] = {1.f-ft, ft};
    int hs[2]  = {h0, h1}; float hwt[2] = {1.f-fh, fh};
    int wss[2] = {w0, w1}; float wwt[2] = {1.f-fw, fw};
    int nb = b*tpn;
    float v0 = 0.f, v1 = 0.f;
    #pragma unroll
    for (int a = 0; a < 2; a++)
        #pragma unroll
        for (int d = 0; d < 2; d++)
            #pragma unroll
            for (int e = 0; e < 2; e++) {
                float wt = twt[a]*hwt[d]*wwt[e];
                int n = ((nb + ts[a])*pn + hs[d])*pn + wss[e];
                int id = (int)(unsigned)(g_key[n] & 0xffffffffull);
                float2 ev = *reinterpret_cast<const float2*>(emb + id*64 + c);
                v0 = fmaf(wt, ev.x, v0);
                v1 = fmaf(wt, ev.y, v1);
            }
    int base = ((b*64 + c)*4 + t)*256 + h*16 + w;
    g_hup[base] = v0;
    g_hup[base + 1024] = v1;
}

// ---- conv3d partial: 16 input channels per block (split-K x4, grid 512) ----
__global__ void __launch_bounds__(256) k_conv_part(int qi) {
    int b = blockIdx.x, t = blockIdx.y;
    int hq = blockIdx.z & 3, part = blockIdx.z >> 2;   // part 0..3
    int tid = threadIdx.x;
    int p = tid & 31;                 // channel pair: c0=p, c1=p+32
    int hh = (tid >> 5) & 3;
    int wseg = tid >> 7;              // 0 or 1
    int h = hq*4 + hh;
    int wbase = wseg << 3;
    __shared__ __align__(16) ull wsu[4][27*32];
    __shared__ __align__(16) ull xsu[4][288];
    ull acc[8];
    #pragma unroll
    for (int i = 0; i < 8; i++) acc[i] = 0ull;
    int cb0 = part << 4;
    for (int cb = cb0; cb < cb0 + 16; cb += 4) {
        __syncthreads();
        const ull* wsrc = g_Wt2 + (size_t)((qi*64 + cb)*27)*32;
        for (int i = tid; i < 4*27*32; i += 256) wsu[0][i] = wsrc[i];
        for (int i = tid; i < 4*288; i += 256) {
            int cib = i / 288, r = i % 288;
            int td = r/96, rem = r%96, hd = rem/16, wd = rem & 15;
            int tt = t + td - 1;
            int hg = hq*4 + hd - 1;
            float x = (tt >= 0 && tt < 4 && hg >= 0 && hg < 16)
                      ? g_hup[((b*64 + cb + cib)*4 + tt)*256 + hg*16 + wd] : 0.f;
            xsu[cib][r] = dup32(x);
        }
        __syncthreads();
        #pragma unroll
        for (int cib = 0; cib < 4; cib++) {
            #pragma unroll
            for (int kd = 0; kd < 3; kd++) {
                #pragma unroll
                for (int kh = 0; kh < 3; kh++) {
                    const ull* xrow = xsu[cib] + (kd*6 + hh + kh)*16;
                    ull r[10];
                    r[0] = (wseg == 0) ? 0ull : xrow[wbase - 1];
                    #pragma unroll
                    for (int j = 1; j <= 8; j++) r[j] = xrow[wbase - 1 + j];
                    r[9] = (wseg == 1) ? 0ull : xrow[wbase + 8];
                    const ull* wp = wsu[cib] + (kd*9 + kh*3)*32 + p;
                    #pragma unroll
                    for (int kw = 0; kw < 3; kw++) {
                        ull wv = wp[kw*32];
                        #pragma unroll
                        for (int w2 = 0; w2 < 8; w2++)
                            FMA2(acc[w2], wv, r[w2+kw]);
                    }
                }
            }
        }
    }
    int base0 = ((b*64 + p     )*4 + t)*256 + h*16 + wbase;
    int base1 = ((b*64 + p + 32)*4 + t)*256 + h*16 + wbase;
    float* dst = g_part[part];
    #pragma unroll
    for (int w2 = 0; w2 < 8; w2++) {
        dst[base0 + w2] = __uint_as_float((unsigned)(acc[w2] & 0xffffffffull));
        dst[base1 + w2] = __uint_as_float((unsigned)(acc[w2] >> 32));
    }
}

// ---- conv epilogue: combine 4 partials, mix, accumulate, commit.
//      last=1: also emit straight-through output + bincount (replaces k_copy) ----
__global__ void __launch_bounds__(256) k_conv_fin(const float* __restrict__ z,
                                                  const float* __restrict__ bq, int qi,
                                                  int last, float* __restrict__ out) {
    int i4 = blockIdx.x*256 + threadIdx.x;   // 0..131071
    int base = i4 << 2;
    float4 p0 = *reinterpret_cast<const float4*>(&g_part[0][base]);
    float4 p1 = *reinterpret_cast<const float4*>(&g_part[1][base]);
    float4 p2 = *reinterpret_cast<const float4*>(&g_part[2][base]);
    float4 p3 = *reinterpret_cast<const float4*>(&g_part[3][base]);
    int c = (base >> 10) & 63;
    float bias = bq[qi*64 + c];
    float4 hv = *reinterpret_cast<const float4*>(&g_hup[base]);
    float4 av = *reinterpret_cast<const float4*>(&g_accu[base]);
    float4 zv = *reinterpret_cast<const float4*>(&z[base]);
    float s0 = ((p0.x + p1.x) + p2.x) + p3.x;
    float s1 = ((p0.y + p1.y) + p2.y) + p3.y;
    float s2 = ((p0.z + p1.z) + p2.z) + p3.z;
    float s3 = ((p0.w + p1.w) + p2.w) + p3.w;
    float4 nv;
    nv.x = av.x + (0.5f*hv.x + 0.5f*(s0 + bias));
    nv.y = av.y + (0.5f*hv.y + 0.5f*(s1 + bias));
    nv.z = av.z + (0.5f*hv.z + 0.5f*(s2 + bias));
    nv.w = av.w + (0.5f*hv.w + 0.5f*(s3 + bias));
    *reinterpret_cast<float4*>(&g_accu[base]) = nv;
    float d0 = nv.x - zv.x, d1 = nv.y - zv.y, d2 = nv.z - zv.z, d3 = nv.w - zv.w;
    if (last) {
        float4 ov;
        ov.x = d0 + zv.x; ov.y = d1 + zv.y; ov.z = d2 + zv.z; ov.w = d3 + zv.w;
        *reinterpret_cast<float4*>(&out[base]) = ov;
        if (i4 < 8192)
            atomicAdd(&g_counts[(int)(unsigned)(g_key[i4] & 0xffffffffull)], 1);
    }
    float lsum = d0*d0 + d1*d1 + d2*d2 + d3*d3;
    #pragma unroll
    for (int o = 16; o; o >>= 1) lsum += __shfl_down_sync(0xffffffffu, lsum, o);
    __shared__ float red[8];
    if ((threadIdx.x & 31) == 0) red[threadIdx.x >> 5] = lsum;
    __syncthreads();
    if (threadIdx.x < 8) {
        float v = red[threadIdx.x];
        #pragma unroll
        for (int o = 4; o; o >>= 1) v += __shfl_down_sync(0xffu, v, o);
        if (threadIdx.x == 0) atomicAdd(&g_commit, v);
    }
}

// ---------------- finalization ----------------
__global__ void k_stats(float* __restrict__ out) {
    int tid = threadIdx.x;
    float ent = 0.f; int cnt = 0;
    for (int i = tid; i < NCODES; i += 256) {
        float p = (float)g_counts[i] * (1.0f/8192.0f);
        out[OFF_USAGE + i] = p;
        ent += p * logf(p + 1e-10f);
        if (p > (1.0f/16384.0f)) cnt++;
    }
    __shared__ float se[256];
    __shared__ int   sc[256];
    se[tid] = ent; sc[tid] = cnt;
    __syncthreads();
    for (int o = 128; o; o >>= 1) {
        if (tid < o) { se[tid] += se[tid+o]; sc[tid] += sc[tid+o]; }
        __syncthreads();
    }
    if (tid == 0) {
        out[OFF_COMMIT] = g_commit * (0.25f/524288.0f) * 0.1f;
        out[OFF_PERP]   = expf(-se[0]);
        out[OFF_AVG]    = (float)sc[0] / 16384.0f;
    }
}

extern "C" void kernel_launch(void* const* d_in, const int* in_sizes, int n_in,
                              void* d_out, int out_size) {
    const float* z   = nullptr;
    const float* emb = nullptr;
    const float* Wq  = nullptr;
    const float* bq  = nullptr;
    for (int i = 0; i < n_in; i++) {
        switch (in_sizes[i]) {
            case 524288:  z   = (const float*)d_in[i]; break;
            case 1048576: emb = (const float*)d_in[i]; break;
            case 442368:  Wq  = (const float*)d_in[i]; break;
            case 256:     bq  = (const float*)d_in[i]; break;
        }
    }
    float* out = (float*)d_out;

    static const int TPN[10] = {1,1,2,2,2,4,4,4,4,4};
    static const int VPN[10] = {1,2,3,4,5,6,8,10,13,16};
    static const int QIA[10] = {0,0,1,1,1,2,2,3,3,3};

    k_setup<<<4096, 256>>>(z, emb, Wq);

    int off = OFF_IDX;
    for (int si = 0; si < 10; si++) {
        int tpn = TPN[si], pn = VPN[si];
        int N = BB * tpn * pn * pn;
        if (si > 0) {
            if (N <= 512)
                k_pool_warp<<<(N*64*32 + 255)/256, 256>>>(z, tpn, pn, N);
            else
                k_pool<<<(N*64 + 255)/256, 256>>>(z, tpn, pn, N);
        }
        dim3 gnn(32, (N + 31)/32), bnn(64, 4);
        k_nn<<<gnn, bnn>>>(N);
        k_upsample<<<(ZSIZE/2 + 255)/256, 256>>>(emb, tpn, pn, N, out + off);
        off += N;
        k_conv_part<<<dim3(8,4,16), 256>>>(QIA[si]);
        k_conv_fin<<<ZSIZE/1024, 256>>>(z, bq, QIA[si], si == 9 ? 1 : 0, out);
    }
    k_stats<<<1, 256>>>(out);
}

// round 13
// speedup vs baseline: 1.0395x; 1.0188x over previous
#include <cuda_runtime.h>
#include <math.h>

#define NCODES 16384
#define CEMB   64
#define BB     8
#define ZSIZE  (BB*CEMB*4*16*16)   /* 524288 */
#define MAXN   8192

#define OFF_COMMIT 524288
#define OFF_PERP   524289
#define OFF_AVG    524290
#define OFF_USAGE  524291
#define OFF_IDX    540675

typedef unsigned long long ull;

__device__ float g_accu[ZSIZE];
__device__ float g_hup[ZSIZE];
__device__ float g_part[4][ZSIZE];
__device__ float g_q[MAXN*CEMB];
__device__ ull   g_key[MAXN];
__device__ float g_embT[CEMB*NCODES];
__device__ float g_esq[NCODES];
__device__ ull   g_Wt2[4*64*27*32];   /* [q][ci][k][pair p] : (c=p, c=p+32) */
__device__ float g_commit;
__device__ int   g_counts[NCODES];

#define FMA2(d,a,b) asm("fma.rn.f32x2 %0, %1, %2, %3;" : "=l"(d) : "l"(a), "l"(b), "l"(d))

__device__ __forceinline__ ull dup32(float v) {
    unsigned u = __float_as_uint(v);
    return ((ull)u << 32) | u;
}

// ---------------- fused setup (also does scale-0 pool: accu==0) ----------------
__global__ void k_setup(const float* __restrict__ z, const float* __restrict__ emb,
                        const float* __restrict__ Wq) {
    int tid = blockIdx.x*256 + threadIdx.x;   // 0..1048575
    {
        int k = tid >> 14, c = tid & (NCODES-1);
        g_embT[tid] = emb[c*CEMB + k];
    }
    if (tid < NCODES) {
        const float4* p = reinterpret_cast<const float4*>(emb + tid*CEMB);
        float s = 0.f;
        #pragma unroll
        for (int i = 0; i < 16; i++) {
            float4 v = p[i];
            s += v.x*v.x + v.y*v.y + v.z*v.z + v.w*v.w;
        }
        g_esq[tid] = s;
        g_counts[tid] = 0;
    }
    if (tid < 4*64*27*32) {
        int p = tid & 31;
        int r = tid >> 5;
        int k = r % 27;
        int r2 = r / 27;
        int ci = r2 % 64;
        int q  = r2 / 64;
        float lo = Wq[((q*64 + p     )*64 + ci)*27 + k];
        float hi = Wq[((q*64 + p + 32)*64 + ci)*27 + k];
        g_Wt2[tid] = ((ull)__float_as_uint(hi) << 32) | __float_as_uint(lo);
    }
    if (tid < ZSIZE) g_accu[tid] = 0.f;
    // scale-0 pool: q[b*64+c] = mean(z[b,c,:,:,:]) ; one warp per (b,c)
    if (tid < 512*32) {
        int lane = tid & 31;
        int gw = tid >> 5;
        int c = gw & 63, b = gw >> 6;
        const float* zp = z + (b*64 + c)*1024;
        float sum = 0.f;
        for (int i = lane; i < 1024; i += 32) sum += zp[i];
        #pragma unroll
        for (int o = 16; o; o >>= 1) sum += __shfl_down_sync(0xffffffffu, sum, o);
        if (lane == 0) g_q[b*64 + c] = sum * (1.0f/1024.0f);
    }
    if (tid < 8) g_key[tid] = 0xFFFFFFFFFFFFFFFFull;
    if (tid == 0) g_commit = 0.f;
}

// ---- pool window bounds ----
__device__ __forceinline__ void pool_bounds(int n, int tpn, int pn,
        int& b, int& sT, int& eT, int& sH, int& eH, int& sW, int& eW) {
    int x = n % pn;
    int v = (n/pn) % pn;
    int r2 = n/(pn*pn);
    int u = r2 % tpn;
    b = r2 / tpn;
    sT = (u*4)/tpn;  eT = ((u+1)*4  + tpn-1)/tpn;
    sH = (v*16)/pn;  eH = ((v+1)*16 + pn-1)/pn;
    sW = (x*16)/pn;  eW = ((x+1)*16 + pn-1)/pn;
}

// -------- pool, thread version (large N / small windows) --------
__global__ void k_pool(const float* __restrict__ z, int tpn, int pn, int N) {
    int tid = blockIdx.x*256 + threadIdx.x;
    if (tid >= N*64) return;
    int c = tid & 63;
    int n = tid >> 6;
    if (c == 0) g_key[n] = 0xFFFFFFFFFFFFFFFFull;
    int b, sT, eT, sH, eH, sW, eW;
    pool_bounds(n, tpn, pn, b, sT, eT, sH, eH, sW, eW);
    const float* zp = z      + (b*64 + c)*1024;
    const float* ap = g_accu + (b*64 + c)*1024;
    float sum = 0.f;
    for (int t = sT; t < eT; t++)
        for (int h = sH; h < eH; h++)
            for (int w = sW; w < eW; w++) {
                int o = t*256 + h*16 + w;
                sum += zp[o] - ap[o];
            }
    float inv = (1.f/(float)(eT-sT))*(1.f/(float)(eH-sH))*(1.f/(float)(eW-sW));
    g_q[n*64 + c] = sum * inv;
}

// -------- pool, warp version (small N / big windows) --------
__global__ void k_pool_warp(const float* __restrict__ z, int tpn, int pn, int N) {
    int gw = (blockIdx.x*256 + threadIdx.x) >> 5;
    int lane = threadIdx.x & 31;
    if (gw >= N*64) return;
    int c = gw & 63;
    int n = gw >> 6;
    if (c == 0 && lane == 0) g_key[n] = 0xFFFFFFFFFFFFFFFFull;
    int b, sT, eT, sH, eH, sW, eW;
    pool_bounds(n, tpn, pn, b, sT, eT, sH, eH, sW, eW);
    int nT = eT-sT, nH = eH-sH, nW = eW-sW;
    int tot = nT*nH*nW;
    const float* zp = z      + (b*64 + c)*1024;
    const float* ap = g_accu + (b*64 + c)*1024;
    float sum = 0.f;
    for (int i = lane; i < tot; i += 32) {
        int w = i % nW;
        int r = i / nW;
        int h = r % nH;
        int t = r / nH;
        int o = (sT+t)*256 + (sH+h)*16 + (sW+w);
        sum += zp[o] - ap[o];
    }
    #pragma unroll
    for (int o = 16; o; o >>= 1) sum += __shfl_down_sync(0xffffffffu, sum, o);
    if (lane == 0) {
        float inv = (1.f/(float)nT)*(1.f/(float)nH)*(1.f/(float)nW);
        g_q[n*64 + c] = sum * inv;
    }
}

// ---- shared: per-query key reduce + atomicMin ----
__device__ __forceinline__ void key_reduce_commit(float best, int bi, int q, int N, int tx) {
    unsigned ub = __float_as_uint(best);
    ub = (ub & 0x80000000u) ? ~ub : (ub | 0x80000000u);
    ull key = ((ull)ub << 32) | (unsigned)bi;
    #pragma unroll
    for (int o = 16; o; o >>= 1) {
        ull ok = __shfl_down_sync(0xffffffffu, key, o);
        if (ok < key) key = ok;
    }
    if ((tx & 31) == 0 && q < N) atomicMin(&g_key[q], key);
}

// -------- NN search: 32 queries x 512 codes per block, packed f32x2 FMA --------
__global__ void __launch_bounds__(256, 2) k_nn(int N) {
    int tx = threadIdx.x;
    int ty = threadIdx.y;
    int qbase = blockIdx.y << 5;
    int cbase = (blockIdx.x << 9) + (tx << 3);
    __shared__ __align__(16) ull qs[32*64];
    int tid = ty*64 + tx;
    for (int i = tid; i < 2048; i += 256) {
        int qr = qbase + (i >> 6);
        qs[i] = dup32((qr < N) ? g_q[qr*64 + (i & 63)] : 0.f);
    }
    __syncthreads();
    ull acc[8][4];
    #pragma unroll
    for (int j = 0; j < 8; j++)
        #pragma unroll
        for (int cc = 0; cc < 4; cc++) acc[j][cc] = 0ull;
    const ulonglong2* e2 = reinterpret_cast<const ulonglong2*>(g_embT);
    int coff = (blockIdx.x << 7) + (tx << 1);
    const ulonglong2* qb2 = reinterpret_cast<const ulonglong2*>(qs) + (ty << 3)*32;
    #pragma unroll 2
    for (int k = 0; k < 64; k += 2) {
        ulonglong2 ea0 = e2[(k << 12) + coff];
        ulonglong2 eb0 = e2[(k << 12) + coff + 1];
        ulonglong2 ea1 = e2[((k+1) << 12) + coff];
        ulonglong2 eb1 = e2[((k+1) << 12) + coff + 1];
        #pragma unroll
        for (int j = 0; j < 8; j++) {
            ulonglong2 qp = qb2[(j << 5) + (k >> 1)];
            FMA2(acc[j][0], qp.x, ea0.x);
            FMA2(acc[j][1], qp.x, ea0.y);
            FMA2(acc[j][2], qp.x, eb0.x);
            FMA2(acc[j][3], qp.x, eb0.y);
            FMA2(acc[j][0], qp.y, ea1.x);
            FMA2(acc[j][1], qp.y, ea1.y);
            FMA2(acc[j][2], qp.y, eb1.x);
            FMA2(acc[j][3], qp.y, eb1.y);
        }
    }
    const float4* s4 = reinterpret_cast<const float4*>(g_esq);
    float4 qa = s4[cbase >> 2];
    float4 qbv = s4[(cbase >> 2) + 1];
    float es[8] = {qa.x, qa.y, qa.z, qa.w, qbv.x, qbv.y, qbv.z, qbv.w};
    #pragma unroll
    for (int j = 0; j < 8; j++) {
        float best = 3.4e38f; int bi = 0;
        #pragma unroll
        for (int cc = 0; cc < 4; cc++) {
            float d0 = __uint_as_float((unsigned)(acc[j][cc] & 0xffffffffull));
            float d1 = __uint_as_float((unsigned)(acc[j][cc] >> 32));
            float s0 = fmaf(-2.f, d0, es[2*cc]);
            float s1 = fmaf(-2.f, d1, es[2*cc+1]);
            if (s0 < best) { best = s0; bi = cbase + 2*cc; }
            if (s1 < best) { best = s1; bi = cbase + 2*cc + 1; }
        }
        key_reduce_commit(best, bi, qbase + (ty << 3) + j, N, tx);
    }
}

// -------- upsample (trilinear), channel-pair per thread, float2 gathers --------
__device__ __forceinline__ void axw(int i, int in, int out, int& i0, int& i1, float& f) {
    float scale = (float)in / (float)out;
    float src = fmaxf((i + 0.5f)*scale - 0.5f, 0.f);
    i0 = (int)src;
    if (i0 > in-1) i0 = in-1;
    i1 = i0 + 1; if (i1 > in-1) i1 = in-1;
    f = src - (float)i0;
}

__global__ void k_upsample(const float* __restrict__ emb, int tpn, int pn, int N,
                           float* __restrict__ idx_out) {
    int tid = blockIdx.x*256 + threadIdx.x;     // 0..262143
    if (tid >= ZSIZE/2) return;
    if (tid < N) idx_out[tid] = (float)(unsigned)(g_key[tid] & 0xffffffffull);
    int c = (tid & 31) << 1;      // channel pair c, c+1
    int s = tid >> 5;
    int w = s & 15, h = (s >> 4) & 15, t = (s >> 8) & 3, b = s >> 10;
    int t0,t1,h0,h1,w0,w1; float ft,fh,fw;
    axw(t, tpn,  4, t0, t1, ft);
    axw(h, pn,  16, h0, h1, fh);
    axw(w, pn,  16, w0, w1, fw);
    int ts[2]  = {t0, t1}; float twt[2] = {1.f-ft, ft};
    int hs[2]  = {h0, h1}; float hwt[2] = {1.f-fh, fh};
    int wss[2] = {w0, w1}; float wwt[2] = {1.f-fw, fw};
    int nb = b*tpn;
    float v0 = 0.f, v1 = 0.f;
    #pragma unroll
    for (int a = 0; a < 2; a++)
        #pragma unroll
        for (int d = 0; d < 2; d++)
            #pragma unroll
            for (int e = 0; e < 2; e++) {
                float wt = twt[a]*hwt[d]*wwt[e];
                int n = ((nb + ts[a])*pn + hs[d])*pn + wss[e];
                int id = (int)(unsigned)(g_key[n] & 0xffffffffull);
                float2 ev = *reinterpret_cast<const float2*>(emb + id*64 + c);
                v0 = fmaf(wt, ev.x, v0);
                v1 = fmaf(wt, ev.y, v1);
            }
    int base = ((b*64 + c)*4 + t)*256 + h*16 + w;
    g_hup[base] = v0;
    g_hup[base + 1024] = v1;
}

// ---- conv3d partial: 16 input channels per block (split-K x4, grid 512),
//      x-tile stored NON-duplicated (halves smem crossbar traffic); dup in regs ----
__global__ void __launch_bounds__(256) k_conv_part(int qi) {
    int b = blockIdx.x, t = blockIdx.y;
    int hq = blockIdx.z & 3, part = blockIdx.z >> 2;   // part 0..3
    int tid = threadIdx.x;
    int p = tid & 31;                 // channel pair: c0=p, c1=p+32
    int hh = (tid >> 5) & 3;
    int wseg = tid >> 7;              // 0 or 1
    int h = hq*4 + hh;
    int wbase = wseg << 3;
    __shared__ __align__(16) ull   wsu[4][27*32];
    __shared__ __align__(16) float xsf[4][288];
    ull acc[8];
    #pragma unroll
    for (int i = 0; i < 8; i++) acc[i] = 0ull;
    int cb0 = part << 4;
    for (int cb = cb0; cb < cb0 + 16; cb += 4) {
        __syncthreads();
        const ull* wsrc = g_Wt2 + (size_t)((qi*64 + cb)*27)*32;
        for (int i = tid; i < 4*27*32; i += 256) wsu[0][i] = wsrc[i];
        for (int i = tid; i < 4*288; i += 256) {
            int cib = i / 288, r = i % 288;
            int td = r/96, rem = r%96, hd = rem/16, wd = rem & 15;
            int tt = t + td - 1;
            int hg = hq*4 + hd - 1;
            xsf[cib][r] = (tt >= 0 && tt < 4 && hg >= 0 && hg < 16)
                      ? g_hup[((b*64 + cb + cib)*4 + tt)*256 + hg*16 + wd] : 0.f;
        }
        __syncthreads();
        #pragma unroll
        for (int cib = 0; cib < 4; cib++) {
            #pragma unroll
            for (int kd = 0; kd < 3; kd++) {
                #pragma unroll
                for (int kh = 0; kh < 3; kh++) {
                    const float* xrow = xsf[cib] + (kd*6 + hh + kh)*16;
                    float rf[10];
                    rf[0] = (wseg == 0) ? 0.f : xrow[wbase - 1];
                    const float4* x4 = reinterpret_cast<const float4*>(xrow + wbase);
                    float4 xa = x4[0], xb = x4[1];
                    rf[1] = xa.x; rf[2] = xa.y; rf[3] = xa.z; rf[4] = xa.w;
                    rf[5] = xb.x; rf[6] = xb.y; rf[7] = xb.z; rf[8] = xb.w;
                    rf[9] = (wseg == 1) ? 0.f : xrow[wbase + 8];
                    ull r[10];
                    #pragma unroll
                    for (int j = 0; j < 10; j++) r[j] = dup32(rf[j]);
                    const ull* wp = wsu[cib] + (kd*9 + kh*3)*32 + p;
                    #pragma unroll
                    for (int kw = 0; kw < 3; kw++) {
                        ull wv = wp[kw*32];
                        #pragma unroll
                        for (int w2 = 0; w2 < 8; w2++)
                            FMA2(acc[w2], wv, r[w2+kw]);
                    }
                }
            }
        }
    }
    int base0 = ((b*64 + p     )*4 + t)*256 + h*16 + wbase;
    int base1 = ((b*64 + p + 32)*4 + t)*256 + h*16 + wbase;
    float* dst = g_part[part];
    #pragma unroll
    for (int w2 = 0; w2 < 8; w2++) {
        dst[base0 + w2] = __uint_as_float((unsigned)(acc[w2] & 0xffffffffull));
        dst[base1 + w2] = __uint_as_float((unsigned)(acc[w2] >> 32));
    }
}

// ---- conv epilogue: combine 4 partials, mix, accumulate, commit.
//      last=1: also emit straight-through output + bincount ----
__global__ void __launch_bounds__(256) k_conv_fin(const float* __restrict__ z,
                                                  const float* __restrict__ bq, int qi,
                                                  int last, float* __restrict__ out) {
    int i4 = blockIdx.x*256 + threadIdx.x;   // 0..131071
    int base = i4 << 2;
    float4 p0 = *reinterpret_cast<const float4*>(&g_part[0][base]);
    float4 p1 = *reinterpret_cast<const float4*>(&g_part[1][base]);
    float4 p2 = *reinterpret_cast<const float4*>(&g_part[2][base]);
    float4 p3 = *reinterpret_cast<const float4*>(&g_part[3][base]);
    int c = (base >> 10) & 63;
    float bias = bq[qi*64 + c];
    float4 hv = *reinterpret_cast<const float4*>(&g_hup[base]);
    float4 av = *reinterpret_cast<const float4*>(&g_accu[base]);
    float4 zv = *reinterpret_cast<const float4*>(&z[base]);
    float s0 = ((p0.x + p1.x) + p2.x) + p3.x;
    float s1 = ((p0.y + p1.y) + p2.y) + p3.y;
    float s2 = ((p0.z + p1.z) + p2.z) + p3.z;
    float s3 = ((p0.w + p1.w) + p2.w) + p3.w;
    float4 nv;
    nv.x = av.x + (0.5f*hv.x + 0.5f*(s0 + bias));
    nv.y = av.y + (0.5f*hv.y + 0.5f*(s1 + bias));
    nv.z = av.z + (0.5f*hv.z + 0.5f*(s2 + bias));
    nv.w = av.w + (0.5f*hv.w + 0.5f*(s3 + bias));
    *reinterpret_cast<float4*>(&g_accu[base]) = nv;
    float d0 = nv.x - zv.x, d1 = nv.y - zv.y, d2 = nv.z - zv.z, d3 = nv.w - zv.w;
    if (last) {
        float4 ov;
        ov.x = d0 + zv.x; ov.y = d1 + zv.y; ov.z = d2 + zv.z; ov.w = d3 + zv.w;
        *reinterpret_cast<float4*>(&out[base]) = ov;
        if (i4 < 8192)
            atomicAdd(&g_counts[(int)(unsigned)(g_key[i4] & 0xffffffffull)], 1);
    }
    float lsum = d0*d0 + d1*d1 + d2*d2 + d3*d3;
    #pragma unroll
    for (int o = 16; o; o >>= 1) lsum += __shfl_down_sync(0xffffffffu, lsum, o);
    __shared__ float red[8];
    if ((threadIdx.x & 31) == 0) red[threadIdx.x >> 5] = lsum;
    __syncthreads();
    if (threadIdx.x < 8) {
        float v = red[threadIdx.x];
        #pragma unroll
        for (int o = 4; o; o >>= 1) v += __shfl_down_sync(0xffu, v, o);
        if (threadIdx.x == 0) atomicAdd(&g_commit, v);
    }
}

// ---------------- finalization ----------------
__global__ void k_stats(float* __restrict__ out) {
    int tid = threadIdx.x;
    float ent = 0.f; int cnt = 0;
    for (int i = tid; i < NCODES; i += 256) {
        float p = (float)g_counts[i] * (1.0f/8192.0f);
        out[OFF_USAGE + i] = p;
        ent += p * logf(p + 1e-10f);
        if (p > (1.0f/16384.0f)) cnt++;
    }
    __shared__ float se[256];
    __shared__ int   sc[256];
    se[tid] = ent; sc[tid] = cnt;
    __syncthreads();
    for (int o = 128; o; o >>= 1) {
        if (tid < o) { se[tid] += se[tid+o]; sc[tid] += sc[tid+o]; }
        __syncthreads();
    }
    if (tid == 0) {
        out[OFF_COMMIT] = g_commit * (0.25f/524288.0f) * 0.1f;
        out[OFF_PERP]   = expf(-se[0]);
        out[OFF_AVG]    = (float)sc[0] / 16384.0f;
    }
}

extern "C" void kernel_launch(void* const* d_in, const int* in_sizes, int n_in,
                              void* d_out, int out_size) {
    const float* z   = nullptr;
    const float* emb = nullptr;
    const float* Wq  = nullptr;
    const float* bq  = nullptr;
    for (int i = 0; i < n_in; i++) {
        switch (in_sizes[i]) {
            case 524288:  z   = (const float*)d_in[i]; break;
            case 1048576: emb = (const float*)d_in[i]; break;
            case 442368:  Wq  = (const float*)d_in[i]; break;
            case 256:     bq  = (const float*)d_in[i]; break;
        }
    }
    float* out = (float*)d_out;

    static const int TPN[10] = {1,1,2,2,2,4,4,4,4,4};
    static const int VPN[10] = {1,2,3,4,5,6,8,10,13,16};
    static const int QIA[10] = {0,0,1,1,1,2,2,3,3,3};

    k_setup<<<4096, 256>>>(z, emb, Wq);

    int off = OFF_IDX;
    for (int si = 0; si < 10; si++) {
        int tpn = TPN[si], pn = VPN[si];
        int N = BB * tpn * pn * pn;
        if (si > 0) {
            if (N <= 512)
                k_pool_warp<<<(N*64*32 + 255)/256, 256>>>(z, tpn, pn, N);
            else
                k_pool<<<(N*64 + 255)/256, 256>>>(z, tpn, pn, N);
        }
        dim3 gnn(32, (N + 31)/32), bnn(64, 4);
        k_nn<<<gnn, bnn>>>(N);
        k_upsample<<<(ZSIZE/2 + 255)/256, 256>>>(emb, tpn, pn, N, out + off);
        off += N;
        k_conv_part<<<dim3(8,4,16), 256>>>(QIA[si]);
        k_conv_fin<<<ZSIZE/1024, 256>>>(z, bq, QIA[si], si == 9 ? 1 : 0, out);
    }
    k_stats<<<1, 256>>>(out);
}